// round 15
// baseline (speedup 1.0000x reference)
#include <cuda_runtime.h>
#include <cuda_fp16.h>
#include <math.h>

#define HID   128
#define MAXN  50000
#define MAXE  800000
#define RNUM  8
#define HEADS 4
#define FFDIM 512

// fp16 weight buffer offsets (halves)
#define OFF_XR   0
#define OFF_ROOT (RNUM*HID*HID)
#define OFF_WATT (OFF_ROOT + HID*HID)
#define OFF_FFN1 (OFF_WATT + HID*HID)
#define OFF_FFN2 (OFF_FFN1 + HID*FFDIM)
#define WH_TOTAL (OFF_FFN2 + FFDIM*HID)

// ---------------- scratch ----------------
__device__ __half   g_h1  [(size_t)MAXN*HID];
__device__ __half   g_xr  [(size_t)RNUM*MAXN*HID];
__device__ float    g_ad  [(size_t)MAXN*64];       // 64 cols: 0-31 src, 32-63 dst
__device__ __half   g_outc[(size_t)MAXN*HID];      // root GEMM + bias (fp16)
__device__ __half   g_h2  [(size_t)MAXN*HID];
__device__ __half   g_t   [(size_t)MAXN*FFDIM];
__device__ float    g_er  [32];
__device__ __half   g_wh  [WH_TOTAL];
// CSR
__device__ int      g_deg [MAXN];
__device__ int      g_start[MAXN];
__device__ int      g_pos [MAXN];
__device__ int      g_cursor;
__device__ int      g_rec [MAXE];

// ---------------- helpers ----------------
__device__ __forceinline__ float geluf(float v) {
    return 0.5f * v * (1.0f + erff(v * 0.7071067811865475f));
}
__device__ __forceinline__ float eluf(float v) {
    return v > 0.0f ? v : expm1f(v);
}
__device__ __forceinline__ float lreluf(float v) {
    return v > 0.0f ? v : 0.2f * v;
}

// ---------------- prep (weights conv + watt + er) ----------------
#define P_W0 0
#define P_W1 (P_W0 + RNUM*HID*HID/4)
#define P_W2 (P_W1 + HID*HID/4)
#define P_W3 (P_W2 + HID*FFDIM/4)
#define P_W4 (P_W3 + FFDIM*HID/4)
#define P_ER (P_W4 + 128*128)
#define P_END (P_ER + 32)
__global__ void prep_kernel(const float* __restrict__ weight,
                            const float* __restrict__ root_w,
                            const float* __restrict__ ffn_w1,
                            const float* __restrict__ ffn_w2,
                            const float* __restrict__ att_src,
                            const float* __restrict__ att_dst,
                            const float* __restrict__ att_edge,
                            const float* __restrict__ emb) {
    int i = blockIdx.x * blockDim.x + threadIdx.x;
    if (i < P_W4) {
        const float* src; __half* dst; int off;
        if (i < P_W1)      { src = weight; dst = g_wh + OFF_XR;   off = i - P_W0; }
        else if (i < P_W2) { src = root_w; dst = g_wh + OFF_ROOT; off = i - P_W1; }
        else if (i < P_W3) { src = ffn_w1; dst = g_wh + OFF_FFN1; off = i - P_W2; }
        else               { src = ffn_w2; dst = g_wh + OFF_FFN2; off = i - P_W3; }
        float4 v = ((const float4*)src)[off];
        __half2 a = __floats2half2_rn(v.x, v.y);
        __half2 b = __floats2half2_rn(v.z, v.w);
        ((uint2*)dst)[off] = make_uint2(*(unsigned*)&a, *(unsigned*)&b);
    } else if (i < P_ER) {
        int idx = i - P_W4;
        int row = idx >> 7, c = idx & 127;
        float s = 0.0f;
        if (c < 64) {
            const float* vec = (c < 32) ? att_src : att_dst;
            int cc = c & 31;
            int r = cc >> 2, h = cc & 3;
            const float* wrow = weight + (long)r * HID * HID + (long)row * HID + h * 32;
            #pragma unroll
            for (int d = 0; d < 32; d++) s += wrow[d] * vec[h * 32 + d];
        }
        g_wh[OFF_WATT + row * 128 + c] = __float2half(s);
    } else if (i < P_END) {
        int t = i - P_ER;
        int r = t >> 2, h = t & 3;
        float s = 0.0f;
        #pragma unroll
        for (int d = 0; d < 32; d++)
            s += emb[r * HID + h * 32 + d] * att_edge[h * 32 + d];
        g_er[t] = s;
    }
}

// ---------------- layernorm (warp per row) -> fp16 out ----------------
__global__ void ln_kernel(const float* __restrict__ x,
                          const float* __restrict__ w,
                          const float* __restrict__ b,
                          __half* __restrict__ out, int Nn) {
    int gw = (blockIdx.x * blockDim.x + threadIdx.x) >> 5;
    int lane = threadIdx.x & 31;
    if (gw >= Nn) return;
    const float4 v = *(const float4*)(x + (size_t)gw * HID + lane * 4);
    float s = v.x + v.y + v.z + v.w;
    float q = v.x * v.x + v.y * v.y + v.z * v.z + v.w * v.w;
    #pragma unroll
    for (int o = 16; o; o >>= 1) {
        s += __shfl_xor_sync(0xffffffffu, s, o);
        q += __shfl_xor_sync(0xffffffffu, q, o);
    }
    float mu = s * (1.0f / HID);
    float var = q * (1.0f / HID) - mu * mu;
    float rstd = rsqrtf(var + 1e-5f);
    float4 wv = *(const float4*)(w + lane * 4);
    float4 bv = *(const float4*)(b + lane * 4);
    __half2 o01 = __floats2half2_rn((v.x - mu) * rstd * wv.x + bv.x,
                                    (v.y - mu) * rstd * wv.y + bv.y);
    __half2 o23 = __floats2half2_rn((v.z - mu) * rstd * wv.z + bv.z,
                                    (v.w - mu) * rstd * wv.w + bv.w);
    *(uint2*)(out + (size_t)gw * HID + lane * 4) =
        make_uint2(*(unsigned*)&o01, *(unsigned*)&o23);
}

// ---------------- CSR build (side stream) ----------------
__global__ void zero_kernel(int Nn) {
    int i = blockIdx.x * blockDim.x + threadIdx.x;
    if (i == 0) g_cursor = 0;
    if (i < Nn) g_deg[i] = 0;
}
__global__ void hist_kernel(const int* __restrict__ ei, int E) {
    int e = blockIdx.x * blockDim.x + threadIdx.x;
    if (e < E) atomicAdd(&g_deg[ei[E + e]], 1);
}
__global__ void alloc_kernel(int Nn) {
    int i = blockIdx.x * blockDim.x + threadIdx.x;
    int lane = threadIdx.x & 31;
    int d = (i < Nn) ? g_deg[i] : 0;
    int sc = d;
    #pragma unroll
    for (int o = 1; o < 32; o <<= 1) {
        int t = __shfl_up_sync(0xffffffffu, sc, o);
        if (lane >= o) sc += t;
    }
    int tot = __shfl_sync(0xffffffffu, sc, 31);
    int base = 0;
    if (lane == 31 && tot) base = atomicAdd(&g_cursor, tot);
    base = __shfl_sync(0xffffffffu, base, 31);
    if (i < Nn) {
        int st = base + sc - d;
        g_start[i] = st;
        g_pos[i] = st;
    }
}
__global__ void scatter_kernel(const int* __restrict__ ei,
                               const int* __restrict__ et, int E) {
    int e = blockIdx.x * blockDim.x + threadIdx.x;
    if (e >= E) return;
    int d = ei[E + e];
    int p = atomicAdd(&g_pos[d], 1);
    g_rec[p] = ei[e] | (et[e] << 16);
}

// -------- fused front GEMM: A resident, loop z=0..9 (watt, xr*8, root) ---------
#define SROW 136
#define SMEM_BYTES (2 * 128 * SROW * 2)

__device__ __forceinline__ const __half* front_B(int z) {
    if (z == 0) return g_wh + OFF_WATT;
    if (z <= 8) return g_wh + OFF_XR + (long)(z - 1) * HID * HID;
    return g_wh + OFF_ROOT;
}

__global__ __launch_bounds__(256, 2)
void gemm_front(const __half* __restrict__ A, const float* __restrict__ bias,
                int M, int Nn) {
    extern __shared__ __half sm[];
    __half* As = sm;
    __half* Bs = sm + 128 * SROW;

    const int m0 = blockIdx.x * 128;
    const int tid = threadIdx.x;
    const int lane = tid & 31, wid = tid >> 5;
    const int wm = wid >> 2, wn = wid & 3;
    const int g = lane >> 2, tg = lane & 3;

    unsigned as_base = (unsigned)__cvta_generic_to_shared(As);
    unsigned bs_base = (unsigned)__cvta_generic_to_shared(Bs);
    const int a_row = (lane & 15);
    const int a_koff = (lane >> 4) << 3;
    const int b_krow = (lane & 15);

    #pragma unroll
    for (int l = 0; l < 8; l++) {
        int idx = tid + l * 256;
        int row = idx >> 4, q = idx & 15;
        bool ok = (m0 + row < M);
        const __half* src = A + (ok ? ((long)(m0 + row) * HID + q * 8) : 0);
        unsigned dst = as_base + ((unsigned)(row * SROW + q * 8) << 1);
        int sz = ok ? 16 : 0;
        asm volatile("cp.async.ca.shared.global [%0], [%1], 16, %2;"
                     :: "r"(dst), "l"(src), "r"(sz));
    }
    {
        const __half* Bz = front_B(0);
        #pragma unroll
        for (int l = 0; l < 8; l++) {
            int idx = tid + l * 256;
            int row = idx >> 4, q = idx & 15;
            unsigned dst = bs_base + ((unsigned)(row * SROW + q * 8) << 1);
            asm volatile("cp.async.ca.shared.global [%0], [%1], 16;"
                         :: "r"(dst), "l"(Bz + (long)row * HID + q * 8));
        }
    }
    asm volatile("cp.async.commit_group;");

    for (int z = 0; z < 10; z++) {
        asm volatile("cp.async.wait_group 0;");
        __syncthreads();

        float acc[4][4][4];
        #pragma unroll
        for (int i = 0; i < 4; i++)
            #pragma unroll
            for (int j = 0; j < 4; j++)
                #pragma unroll
                for (int c = 0; c < 4; c++) acc[i][j][c] = 0.0f;

        #pragma unroll
        for (int kk = 0; kk < 8; kk++) {
            const int k16 = kk * 16;
            unsigned af[4][4], bf[4][2];
            #pragma unroll
            for (int tm = 0; tm < 4; tm++) {
                int rb = wm * 64 + tm * 16;
                unsigned addr = as_base + (((rb + a_row) * SROW + k16 + a_koff) << 1);
                asm volatile(
                    "ldmatrix.sync.aligned.m8n8.x4.shared.b16 {%0,%1,%2,%3}, [%4];"
                    : "=r"(af[tm][0]), "=r"(af[tm][1]),
                      "=r"(af[tm][2]), "=r"(af[tm][3])
                    : "r"(addr));
            }
            #pragma unroll
            for (int tn = 0; tn < 4; tn++) {
                int cb = wn * 32 + tn * 8;
                unsigned addr = bs_base + (((k16 + b_krow) * SROW + cb) << 1);
                asm volatile(
                    "ldmatrix.sync.aligned.m8n8.x2.trans.shared.b16 {%0,%1}, [%2];"
                    : "=r"(bf[tn][0]), "=r"(bf[tn][1])
                    : "r"(addr));
            }
            #pragma unroll
            for (int tm = 0; tm < 4; tm++)
                #pragma unroll
                for (int tn = 0; tn < 4; tn++) {
                    asm volatile(
                        "mma.sync.aligned.m16n8k16.row.col.f32.f16.f16.f32 "
                        "{%0,%1,%2,%3}, {%4,%5,%6,%7}, {%8,%9}, {%0,%1,%2,%3};"
                        : "+f"(acc[tm][tn][0]), "+f"(acc[tm][tn][1]),
                          "+f"(acc[tm][tn][2]), "+f"(acc[tm][tn][3])
                        : "r"(af[tm][0]), "r"(af[tm][1]),
                          "r"(af[tm][2]), "r"(af[tm][3]),
                          "r"(bf[tn][0]), "r"(bf[tn][1]));
                }
        }
        __syncthreads();

        if (z < 9) {
            const __half* Bz = front_B(z + 1);
            #pragma unroll
            for (int l = 0; l < 8; l++) {
                int idx = tid + l * 256;
                int row = idx >> 4, q = idx & 15;
                unsigned dst = bs_base + ((unsigned)(row * SROW + q * 8) << 1);
                asm volatile("cp.async.ca.shared.global [%0], [%1], 16;"
                             :: "r"(dst), "l"(Bz + (long)row * HID + q * 8));
            }
            asm volatile("cp.async.commit_group;");
        }

        #pragma unroll
        for (int tm = 0; tm < 4; tm++) {
            int r0 = m0 + wm * 64 + tm * 16 + g;
            #pragma unroll
            for (int tn = 0; tn < 4; tn++) {
                int col = wn * 32 + tn * 8 + 2 * tg;
                float2 bv = make_float2(0.f, 0.f);
                if (z == 9) bv = *(const float2*)(bias + col);
                #pragma unroll
                for (int half_ = 0; half_ < 2; half_++) {
                    int row = r0 + half_ * 8;
                    if (row >= M) continue;
                    float v0 = acc[tm][tn][half_*2+0] + bv.x;
                    float v1 = acc[tm][tn][half_*2+1] + bv.y;
                    if (z >= 1 && z <= 8) {
                        __half* Ch = g_xr + (long)(z - 1) * Nn * HID;
                        __half2 hv = __floats2half2_rn(v0, v1);
                        *(__half2*)(Ch + (long)row * HID + col) = hv;
                    } else if (z == 0) {
                        if (col < 64)
                            *(float2*)(g_ad + (long)row * 64 + col) = make_float2(v0, v1);
                    } else {
                        __half2 hv = __floats2half2_rn(v0, v1);
                        *(__half2*)(g_outc + (long)row * HID + col) = hv;
                    }
                }
            }
        }
    }
}

// -------- FFN1: A resident (K=128), loop 4 n-tiles; GELU -> g_t fp16 ----------
__global__ __launch_bounds__(256, 2)
void gemm_ffn1(const __half* __restrict__ A, const float* __restrict__ bias,
               int M) {
    extern __shared__ __half sm[];
    __half* As = sm;
    __half* Bs = sm + 128 * SROW;

    const int m0 = blockIdx.x * 128;
    const int tid = threadIdx.x;
    const int lane = tid & 31, wid = tid >> 5;
    const int wm = wid >> 2, wn = wid & 3;
    const int g = lane >> 2, tg = lane & 3;

    unsigned as_base = (unsigned)__cvta_generic_to_shared(As);
    unsigned bs_base = (unsigned)__cvta_generic_to_shared(Bs);
    const int a_row = (lane & 15);
    const int a_koff = (lane >> 4) << 3;
    const int b_krow = (lane & 15);

    #pragma unroll
    for (int l = 0; l < 8; l++) {
        int idx = tid + l * 256;
        int row = idx >> 4, q = idx & 15;
        bool ok = (m0 + row < M);
        const __half* src = A + (ok ? ((long)(m0 + row) * HID + q * 8) : 0);
        unsigned dst = as_base + ((unsigned)(row * SROW + q * 8) << 1);
        int sz = ok ? 16 : 0;
        asm volatile("cp.async.ca.shared.global [%0], [%1], 16, %2;"
                     :: "r"(dst), "l"(src), "r"(sz));
    }
    {
        const __half* B0 = g_wh + OFF_FFN1;
        #pragma unroll
        for (int l = 0; l < 8; l++) {
            int idx = tid + l * 256;
            int row = idx >> 4, q = idx & 15;
            unsigned dst = bs_base + ((unsigned)(row * SROW + q * 8) << 1);
            asm volatile("cp.async.ca.shared.global [%0], [%1], 16;"
                         :: "r"(dst), "l"(B0 + (long)row * FFDIM + q * 8));
        }
    }
    asm volatile("cp.async.commit_group;");

    for (int nt = 0; nt < 4; nt++) {
        asm volatile("cp.async.wait_group 0;");
        __syncthreads();

        float acc[4][4][4];
        #pragma unroll
        for (int i = 0; i < 4; i++)
            #pragma unroll
            for (int j = 0; j < 4; j++)
                #pragma unroll
                for (int c = 0; c < 4; c++) acc[i][j][c] = 0.0f;

        #pragma unroll
        for (int kk = 0; kk < 8; kk++) {
            const int k16 = kk * 16;
            unsigned af[4][4], bf[4][2];
            #pragma unroll
            for (int tm = 0; tm < 4; tm++) {
                int rb = wm * 64 + tm * 16;
                unsigned addr = as_base + (((rb + a_row) * SROW + k16 + a_koff) << 1);
                asm volatile(
                    "ldmatrix.sync.aligned.m8n8.x4.shared.b16 {%0,%1,%2,%3}, [%4];"
                    : "=r"(af[tm][0]), "=r"(af[tm][1]),
                      "=r"(af[tm][2]), "=r"(af[tm][3])
                    : "r"(addr));
            }
            #pragma unroll
            for (int tn = 0; tn < 4; tn++) {
                int cb = wn * 32 + tn * 8;
                unsigned addr = bs_base + (((k16 + b_krow) * SROW + cb) << 1);
                asm volatile(
                    "ldmatrix.sync.aligned.m8n8.x2.trans.shared.b16 {%0,%1}, [%2];"
                    : "=r"(bf[tn][0]), "=r"(bf[tn][1])
                    : "r"(addr));
            }
            #pragma unroll
            for (int tm = 0; tm < 4; tm++)
                #pragma unroll
                for (int tn = 0; tn < 4; tn++) {
                    asm volatile(
                        "mma.sync.aligned.m16n8k16.row.col.f32.f16.f16.f32 "
                        "{%0,%1,%2,%3}, {%4,%5,%6,%7}, {%8,%9}, {%0,%1,%2,%3};"
                        : "+f"(acc[tm][tn][0]), "+f"(acc[tm][tn][1]),
                          "+f"(acc[tm][tn][2]), "+f"(acc[tm][tn][3])
                        : "r"(af[tm][0]), "r"(af[tm][1]),
                          "r"(af[tm][2]), "r"(af[tm][3]),
                          "r"(bf[tn][0]), "r"(bf[tn][1]));
                }
        }
        __syncthreads();

        if (nt < 3) {
            const __half* Bn = g_wh + OFF_FFN1 + (nt + 1) * 128;
            #pragma unroll
            for (int l = 0; l < 8; l++) {
                int idx = tid + l * 256;
                int row = idx >> 4, q = idx & 15;
                unsigned dst = bs_base + ((unsigned)(row * SROW + q * 8) << 1);
                asm volatile("cp.async.ca.shared.global [%0], [%1], 16;"
                             :: "r"(dst), "l"(Bn + (long)row * FFDIM + q * 8));
            }
            asm volatile("cp.async.commit_group;");
        }

        #pragma unroll
        for (int tm = 0; tm < 4; tm++) {
            int r0 = m0 + wm * 64 + tm * 16 + g;
            #pragma unroll
            for (int tn = 0; tn < 4; tn++) {
                int col = nt * 128 + wn * 32 + tn * 8 + 2 * tg;
                float2 bv = *(const float2*)(bias + col);
                #pragma unroll
                for (int half_ = 0; half_ < 2; half_++) {
                    int row = r0 + half_ * 8;
                    if (row >= M) continue;
                    float v0 = geluf(acc[tm][tn][half_*2+0] + bv.x);
                    float v1 = geluf(acc[tm][tn][half_*2+1] + bv.y);
                    __half2 hv = __floats2half2_rn(v0, v1);
                    *(__half2*)(g_t + (long)row * FFDIM + col) = hv;
                }
            }
        }
    }
}

// ---------------- generic fp16 GEMM (FFN2: K=512, ncols=128) ----------------
__global__ __launch_bounds__(256, 2)
void gemm_f16(const __half* __restrict__ A, const __half* __restrict__ B,
              void* __restrict__ C, const float* __restrict__ bias,
              const float* __restrict__ resid,
              int M, int K, int ncols, int act, int outHalf) {
    extern __shared__ __half sm[];
    __half* As = sm;
    __half* Bs = sm + 128 * SROW;

    const int m0 = blockIdx.x * 128;
    const int n0 = blockIdx.y * 128;
    const int tid = threadIdx.x;
    const int lane = tid & 31, wid = tid >> 5;
    const int wm = wid >> 2, wn = wid & 3;
    const int g = lane >> 2, tg = lane & 3;

    float acc[4][4][4];
    #pragma unroll
    for (int i = 0; i < 4; i++)
        #pragma unroll
        for (int j = 0; j < 4; j++)
            #pragma unroll
            for (int c = 0; c < 4; c++) acc[i][j][c] = 0.0f;

    unsigned as_base = (unsigned)__cvta_generic_to_shared(As);
    unsigned bs_base = (unsigned)__cvta_generic_to_shared(Bs);
    const int a_row = (lane & 15);
    const int a_koff = (lane >> 4) << 3;
    const int b_krow = (lane & 15);

    for (int k0 = 0; k0 < K; k0 += 128) {
        if (k0) __syncthreads();
        #pragma unroll
        for (int l = 0; l < 8; l++) {
            int idx = tid + l * 256;
            int row = idx >> 4, q = idx & 15;
            bool ok = (m0 + row < M);
            const __half* src = A + (ok ? ((long)(m0 + row) * K + k0 + q * 8) : 0);
            unsigned dst = as_base + ((unsigned)(row * SROW + q * 8) << 1);
            int sz = ok ? 16 : 0;
            asm volatile("cp.async.ca.shared.global [%0], [%1], 16, %2;"
                         :: "r"(dst), "l"(src), "r"(sz));
        }
        #pragma unroll
        for (int l = 0; l < 8; l++) {
            int idx = tid + l * 256;
            int row = idx >> 4, q = idx & 15;
            const __half* src = B + (long)(k0 + row) * ncols + n0 + q * 8;
            unsigned dst = bs_base + ((unsigned)(row * SROW + q * 8) << 1);
            asm volatile("cp.async.ca.shared.global [%0], [%1], 16;"
                         :: "r"(dst), "l"(src));
        }
        asm volatile("cp.async.commit_group;");
        asm volatile("cp.async.wait_group 0;");
        __syncthreads();

        #pragma unroll
        for (int kk = 0; kk < 8; kk++) {
            const int k16 = kk * 16;
            unsigned af[4][4], bf[4][2];
            #pragma unroll
            for (int tm = 0; tm < 4; tm++) {
                int rb = wm * 64 + tm * 16;
                unsigned addr = as_base + (((rb + a_row) * SROW + k16 + a_koff) << 1);
                asm volatile(
                    "ldmatrix.sync.aligned.m8n8.x4.shared.b16 {%0,%1,%2,%3}, [%4];"
                    : "=r"(af[tm][0]), "=r"(af[tm][1]),
                      "=r"(af[tm][2]), "=r"(af[tm][3])
                    : "r"(addr));
            }
            #pragma unroll
            for (int tn = 0; tn < 4; tn++) {
                int cb = wn * 32 + tn * 8;
                unsigned addr = bs_base + (((k16 + b_krow) * SROW + cb) << 1);
                asm volatile(
                    "ldmatrix.sync.aligned.m8n8.x2.trans.shared.b16 {%0,%1}, [%2];"
                    : "=r"(bf[tn][0]), "=r"(bf[tn][1])
                    : "r"(addr));
            }
            #pragma unroll
            for (int tm = 0; tm < 4; tm++)
                #pragma unroll
                for (int tn = 0; tn < 4; tn++) {
                    asm volatile(
                        "mma.sync.aligned.m16n8k16.row.col.f32.f16.f16.f32 "
                        "{%0,%1,%2,%3}, {%4,%5,%6,%7}, {%8,%9}, {%0,%1,%2,%3};"
                        : "+f"(acc[tm][tn][0]), "+f"(acc[tm][tn][1]),
                          "+f"(acc[tm][tn][2]), "+f"(acc[tm][tn][3])
                        : "r"(af[tm][0]), "r"(af[tm][1]),
                          "r"(af[tm][2]), "r"(af[tm][3]),
                          "r"(bf[tn][0]), "r"(bf[tn][1]));
                }
        }
    }

    #pragma unroll
    for (int tm = 0; tm < 4; tm++) {
        int r0 = m0 + wm * 64 + tm * 16 + g;
        #pragma unroll
        for (int tn = 0; tn < 4; tn++) {
            int col = n0 + wn * 32 + tn * 8 + 2 * tg;
            float2 bv = make_float2(0.f, 0.f);
            if (bias) bv = *(const float2*)(bias + col);
            #pragma unroll
            for (int half_ = 0; half_ < 2; half_++) {
                int row = r0 + half_ * 8;
                if (row >= M) continue;
                float v0 = acc[tm][tn][half_*2+0] + bv.x;
                float v1 = acc[tm][tn][half_*2+1] + bv.y;
                if (act == 1) { v0 = geluf(v0); v1 = geluf(v1); }
                if (resid) {
                    float2 rr = *(const float2*)(resid + (long)row * ncols + col);
                    v0 += rr.x; v1 += rr.y;
                }
                if (outHalf) {
                    __half2 hv = __floats2half2_rn(v0, v1);
                    *(__half2*)((__half*)C + (long)row * ncols + col) = hv;
                } else {
                    *(float2*)((float*)C + (long)row * ncols + col) = make_float2(v0, v1);
                }
            }
        }
    }
}

// ------ fused aggregation: 2 warps per node, streaming cache hints ------
__global__ void aggregate_kernel(const float* __restrict__ x,
                                 const float* __restrict__ w,
                                 const float* __restrict__ b,
                                 float* __restrict__ x1out, int Nn) {
    __shared__ float sh[4][32][5];    // odd-warp partials per node-in-block
    int tid = threadIdx.x, wid = tid >> 5, lane = tid & 31;
    long gw2 = (long)blockIdx.x * 8 + wid;
    long node = gw2 >> 1;
    int half = (int)(gw2 & 1);
    bool active = node < Nn;
    int h = lane >> 3;

    float adv = 0.0f;
    int beg = 0, end = 0;
    if (active) {
        adv = g_ad[node * 64 + 32 + lane] + g_er[lane];
        int s0 = g_start[node];
        int dg = g_deg[node];
        int mid = s0 + ((dg + 1) >> 1);
        beg = half ? mid : s0;
        end = half ? (s0 + dg) : mid;
    }

    float den = 0.0f;
    float a0 = 0.f, a1 = 0.f, a2 = 0.f, a3 = 0.f;
    int e = beg;
    for (; e + 4 <= end; e += 4) {
        int rec[4];
        #pragma unroll
        for (int j = 0; j < 4; j++) rec[j] = __ldcs(&g_rec[e + j]);
        int sidx[4], ridx[4];
        float ads[4];
        uint2 raw[4];
        #pragma unroll
        for (int j = 0; j < 4; j++) {
            sidx[j] = rec[j] & 0xFFFF;
            ridx[j] = rec[j] >> 16;
            ads[j] = __ldg(&g_ad[(long)sidx[j] * 64 + ridx[j] * 4 + h]);
            raw[j] = *(const uint2*)(g_xr + ((long)ridx[j] * Nn + sidx[j]) * HID + lane * 4);
        }
        #pragma unroll
        for (int j = 0; j < 4; j++) {
            float logit = __shfl_sync(0xffffffffu, adv, ridx[j] * 4 + h) + ads[j];
            float ex = __expf(lreluf(logit));
            den += ex;
            float2 p01 = __half22float2(*(__half2*)&raw[j].x);
            float2 p23 = __half22float2(*(__half2*)&raw[j].y);
            a0 += p01.x * ex; a1 += p01.y * ex;
            a2 += p23.x * ex; a3 += p23.y * ex;
        }
    }
    for (; e < end; e++) {
        int rec = __ldcs(&g_rec[e]);
        int s = rec & 0xFFFF, r = rec >> 16;
        float logit = __shfl_sync(0xffffffffu, adv, r * 4 + h)
                    + __ldg(&g_ad[(long)s * 64 + r * 4 + h]);
        float ex = __expf(lreluf(logit));
        den += ex;
        uint2 raw = *(const uint2*)(g_xr + ((long)r * Nn + s) * HID + lane * 4);
        float2 p01 = __half22float2(*(__half2*)&raw.x);
        float2 p23 = __half22float2(*(__half2*)&raw.y);
        a0 += p01.x * ex; a1 += p01.y * ex;
        a2 += p23.x * ex; a3 += p23.y * ex;
    }

    if (half == 1) {
        float* p = sh[wid >> 1][lane];
        p[0] = den; p[1] = a0; p[2] = a1; p[3] = a2; p[4] = a3;
    }
    __syncthreads();
    if (!active || half == 1) return;
    {
        float* p = sh[wid >> 1][lane];
        den += p[0]; a0 += p[1]; a1 += p[2]; a2 += p[3]; a3 += p[4];
    }

    float inv = 1.0f / (den + 1e-16f);
    uint2 rtr = __ldcs((const uint2*)(g_outc + (size_t)node * HID + lane * 4));
    float2 r01 = __half22float2(*(__half2*)&rtr.x);
    float2 r23 = __half22float2(*(__half2*)&rtr.y);
    float4 oc;
    oc.x = eluf(a0 * inv + r01.x);
    oc.y = eluf(a1 * inv + r01.y);
    oc.z = eluf(a2 * inv + r23.x);
    oc.w = eluf(a3 * inv + r23.y);
    float4 xv = __ldcs((const float4*)(x + (size_t)node * HID + lane * 4));
    float4 x1 = make_float4(xv.x + oc.x, xv.y + oc.y, xv.z + oc.z, xv.w + oc.w);
    __stcs((float4*)(x1out + (size_t)node * HID + lane * 4), x1);
    float s = x1.x + x1.y + x1.z + x1.w;
    float q = x1.x * x1.x + x1.y * x1.y + x1.z * x1.z + x1.w * x1.w;
    #pragma unroll
    for (int o = 16; o; o >>= 1) {
        s += __shfl_xor_sync(0xffffffffu, s, o);
        q += __shfl_xor_sync(0xffffffffu, q, o);
    }
    float mu = s * (1.0f / HID);
    float var = q * (1.0f / HID) - mu * mu;
    float rstd = rsqrtf(var + 1e-5f);
    float4 wv = *(const float4*)(w + lane * 4);
    float4 bv = *(const float4*)(b + lane * 4);
    __half2 o01 = __floats2half2_rn((x1.x - mu) * rstd * wv.x + bv.x,
                                    (x1.y - mu) * rstd * wv.y + bv.y);
    __half2 o23 = __floats2half2_rn((x1.z - mu) * rstd * wv.z + bv.z,
                                    (x1.w - mu) * rstd * wv.w + bv.w);
    *(uint2*)(g_h2 + (size_t)node * HID + lane * 4) =
        make_uint2(*(unsigned*)&o01, *(unsigned*)&o23);
}

// ---------------- launch ----------------
extern "C" void kernel_launch(void* const* d_in, const int* in_sizes, int n_in,
                              void* d_out, int out_size) {
    const float* x          = (const float*)d_in[0];
    const float* weight     = (const float*)d_in[1];
    const float* root_w     = (const float*)d_in[2];
    const float* edge_emb   = (const float*)d_in[3];
    const float* att_src    = (const float*)d_in[4];
    const float* att_dst    = (const float*)d_in[5];
    const float* att_edge   = (const float*)d_in[6];
    const float* bias       = (const float*)d_in[7];
    const float* n1w        = (const float*)d_in[8];
    const float* n1b        = (const float*)d_in[9];
    const float* n2w        = (const float*)d_in[10];
    const float* n2b        = (const float*)d_in[11];
    const float* ffn_w1     = (const float*)d_in[12];
    const float* ffn_b1     = (const float*)d_in[13];
    const float* ffn_w2     = (const float*)d_in[14];
    const float* ffn_b2     = (const float*)d_in[15];
    const int*   edge_index = (const int*)d_in[16];
    const int*   edge_type  = (const int*)d_in[17];
    float* out = (float*)d_out;

    int N = in_sizes[0] / HID;
    int E = in_sizes[17];

    static cudaStream_t s2 = nullptr;
    static cudaEvent_t ev_start = nullptr, ev_prep = nullptr, ev_csr = nullptr;
    if (!s2) {
        cudaFuncSetAttribute(gemm_front,
            cudaFuncAttributeMaxDynamicSharedMemorySize, SMEM_BYTES);
        cudaFuncSetAttribute(gemm_ffn1,
            cudaFuncAttributeMaxDynamicSharedMemorySize, SMEM_BYTES);
        cudaFuncSetAttribute(gemm_f16,
            cudaFuncAttributeMaxDynamicSharedMemorySize, SMEM_BYTES);
        cudaStreamCreateWithFlags(&s2, cudaStreamNonBlocking);
        cudaEventCreateWithFlags(&ev_start, cudaEventDisableTiming);
        cudaEventCreateWithFlags(&ev_prep, cudaEventDisableTiming);
        cudaEventCreateWithFlags(&ev_csr, cudaEventDisableTiming);
    }

    __half *p_h1, *p_h2, *p_t, *p_wh;
    cudaGetSymbolAddress((void**)&p_h1, g_h1);
    cudaGetSymbolAddress((void**)&p_h2, g_h2);
    cudaGetSymbolAddress((void**)&p_t,  g_t);
    cudaGetSymbolAddress((void**)&p_wh, g_wh);

    int rowBlocks = (N + 7) / 8;
    int mTiles    = (N + 127) / 128;
    int aggBlocks = (int)((2L * N + 7) / 8);

    // fork: prep + CSR chain on s2
    cudaEventRecord(ev_start, 0);
    cudaStreamWaitEvent(s2, ev_start, 0);
    prep_kernel<<<(P_END + 255) / 256, 256, 0, s2>>>(
        weight, root_w, ffn_w1, ffn_w2, att_src, att_dst, att_edge, edge_emb);
    cudaEventRecord(ev_prep, s2);
    zero_kernel<<<(N + 255) / 256, 256, 0, s2>>>(N);
    hist_kernel<<<(E + 255) / 256, 256, 0, s2>>>(edge_index, E);
    alloc_kernel<<<(N + 255) / 256, 256, 0, s2>>>(N);
    scatter_kernel<<<(E + 255) / 256, 256, 0, s2>>>(edge_index, edge_type, E);
    cudaEventRecord(ev_csr, s2);

    // main stream: LN || prep, then front GEMM
    ln_kernel<<<rowBlocks, 256>>>(x, n1w, n1b, p_h1, N);
    cudaStreamWaitEvent(0, ev_prep, 0);
    gemm_front<<<mTiles, 256, SMEM_BYTES>>>(p_h1, bias, N, N);

    cudaStreamWaitEvent(0, ev_csr, 0);
    aggregate_kernel<<<aggBlocks, 256>>>(x, n2w, n2b, out, N);

    gemm_ffn1<<<mTiles, 256, SMEM_BYTES>>>(p_h2, ffn_b1, N);
    gemm_f16<<<dim3(mTiles, 1, 1), 256, SMEM_BYTES>>>(
        p_t, p_wh + OFF_FFN2, out, ffn_b2, out, N, FFDIM, HID, 0, 0);
}

// round 16
// speedup vs baseline: 1.1063x; 1.1063x over previous
#include <cuda_runtime.h>
#include <cuda_fp16.h>
#include <math.h>

#define HID   128
#define MAXN  50000
#define MAXE  800000
#define RNUM  8
#define HEADS 4
#define FFDIM 512

#define OFF_XR   0
#define OFF_ROOT (RNUM*HID*HID)
#define OFF_WATT (OFF_ROOT + HID*HID)
#define OFF_FFN1 (OFF_WATT + HID*HID)
#define OFF_FFN2 (OFF_FFN1 + HID*FFDIM)
#define WH_TOTAL (OFF_FFN2 + FFDIM*HID)

// ---------------- scratch ----------------
__device__ __half   g_h1  [(size_t)MAXN*HID];
__device__ __half   g_xr  [(size_t)RNUM*MAXN*HID];
__device__ float    g_ad  [(size_t)MAXN*64];
__device__ __half   g_outc[(size_t)MAXN*HID];
__device__ __half   g_h2  [(size_t)MAXN*HID];
__device__ __half   g_t   [(size_t)MAXN*FFDIM];
__device__ float    g_er  [32];
__device__ __half   g_wh  [WH_TOTAL];
// CSR
__device__ int      g_deg [MAXN];
__device__ int      g_start[MAXN];
__device__ int      g_pos [MAXN];
__device__ int      g_cursor;
__device__ int      g_rec [MAXE];

// ---------------- helpers ----------------
__device__ __forceinline__ float geluf(float v) {
    return 0.5f * v * (1.0f + erff(v * 0.7071067811865475f));
}
__device__ __forceinline__ float eluf(float v) {
    return v > 0.0f ? v : expm1f(v);
}
__device__ __forceinline__ float lreluf(float v) {
    return v > 0.0f ? v : 0.2f * v;
}

// ---------------- prep ----------------
#define P_W0 0
#define P_W1 (P_W0 + RNUM*HID*HID/4)
#define P_W2 (P_W1 + HID*HID/4)
#define P_W3 (P_W2 + HID*FFDIM/4)
#define P_W4 (P_W3 + FFDIM*HID/4)
#define P_ER (P_W4 + 128*128)
#define P_END (P_ER + 32)
__global__ void prep_kernel(const float* __restrict__ weight,
                            const float* __restrict__ root_w,
                            const float* __restrict__ ffn_w1,
                            const float* __restrict__ ffn_w2,
                            const float* __restrict__ att_src,
                            const float* __restrict__ att_dst,
                            const float* __restrict__ att_edge,
                            const float* __restrict__ emb) {
    int i = blockIdx.x * blockDim.x + threadIdx.x;
    if (i < P_W4) {
        const float* src; __half* dst; int off;
        if (i < P_W1)      { src = weight; dst = g_wh + OFF_XR;   off = i - P_W0; }
        else if (i < P_W2) { src = root_w; dst = g_wh + OFF_ROOT; off = i - P_W1; }
        else if (i < P_W3) { src = ffn_w1; dst = g_wh + OFF_FFN1; off = i - P_W2; }
        else               { src = ffn_w2; dst = g_wh + OFF_FFN2; off = i - P_W3; }
        float4 v = ((const float4*)src)[off];
        __half2 a = __floats2half2_rn(v.x, v.y);
        __half2 b = __floats2half2_rn(v.z, v.w);
        ((uint2*)dst)[off] = make_uint2(*(unsigned*)&a, *(unsigned*)&b);
    } else if (i < P_ER) {
        int idx = i - P_W4;
        int row = idx >> 7, c = idx & 127;
        float s = 0.0f;
        if (c < 64) {
            const float* vec = (c < 32) ? att_src : att_dst;
            int cc = c & 31;
            int r = cc >> 2, h = cc & 3;
            const float* wrow = weight + (long)r * HID * HID + (long)row * HID + h * 32;
            #pragma unroll
            for (int d = 0; d < 32; d++) s += wrow[d] * vec[h * 32 + d];
        }
        g_wh[OFF_WATT + row * 128 + c] = __float2half(s);
    } else if (i < P_END) {
        int t = i - P_ER;
        int r = t >> 2, h = t & 3;
        float s = 0.0f;
        #pragma unroll
        for (int d = 0; d < 32; d++)
            s += emb[r * HID + h * 32 + d] * att_edge[h * 32 + d];
        g_er[t] = s;
    }
}

// ---------------- layernorm ----------------
__global__ void ln_kernel(const float* __restrict__ x,
                          const float* __restrict__ w,
                          const float* __restrict__ b,
                          __half* __restrict__ out, int Nn) {
    int gw = (blockIdx.x * blockDim.x + threadIdx.x) >> 5;
    int lane = threadIdx.x & 31;
    if (gw >= Nn) return;
    const float4 v = *(const float4*)(x + (size_t)gw * HID + lane * 4);
    float s = v.x + v.y + v.z + v.w;
    float q = v.x * v.x + v.y * v.y + v.z * v.z + v.w * v.w;
    #pragma unroll
    for (int o = 16; o; o >>= 1) {
        s += __shfl_xor_sync(0xffffffffu, s, o);
        q += __shfl_xor_sync(0xffffffffu, q, o);
    }
    float mu = s * (1.0f / HID);
    float var = q * (1.0f / HID) - mu * mu;
    float rstd = rsqrtf(var + 1e-5f);
    float4 wv = *(const float4*)(w + lane * 4);
    float4 bv = *(const float4*)(b + lane * 4);
    __half2 o01 = __floats2half2_rn((v.x - mu) * rstd * wv.x + bv.x,
                                    (v.y - mu) * rstd * wv.y + bv.y);
    __half2 o23 = __floats2half2_rn((v.z - mu) * rstd * wv.z + bv.z,
                                    (v.w - mu) * rstd * wv.w + bv.w);
    *(uint2*)(out + (size_t)gw * HID + lane * 4) =
        make_uint2(*(unsigned*)&o01, *(unsigned*)&o23);
}

// ---------------- CSR build ----------------
__global__ void zero_kernel(int Nn) {
    int i = blockIdx.x * blockDim.x + threadIdx.x;
    if (i == 0) g_cursor = 0;
    if (i < Nn) g_deg[i] = 0;
}
__global__ void hist_kernel(const int* __restrict__ ei, int E) {
    int e = blockIdx.x * blockDim.x + threadIdx.x;
    if (e < E) atomicAdd(&g_deg[ei[E + e]], 1);
}
__global__ void alloc_kernel(int Nn) {
    int i = blockIdx.x * blockDim.x + threadIdx.x;
    int lane = threadIdx.x & 31;
    int d = (i < Nn) ? g_deg[i] : 0;
    int sc = d;
    #pragma unroll
    for (int o = 1; o < 32; o <<= 1) {
        int t = __shfl_up_sync(0xffffffffu, sc, o);
        if (lane >= o) sc += t;
    }
    int tot = __shfl_sync(0xffffffffu, sc, 31);
    int base = 0;
    if (lane == 31 && tot) base = atomicAdd(&g_cursor, tot);
    base = __shfl_sync(0xffffffffu, base, 31);
    if (i < Nn) {
        int st = base + sc - d;
        g_start[i] = st;
        g_pos[i] = st;
    }
}
__global__ void scatter_kernel(const int* __restrict__ ei,
                               const int* __restrict__ et, int E) {
    int e = blockIdx.x * blockDim.x + threadIdx.x;
    if (e >= E) return;
    int d = ei[E + e];
    int p = atomicAdd(&g_pos[d], 1);
    g_rec[p] = ei[e] | (et[e] << 16);
}

// -------- fused front GEMM ---------
#define SROW 136
#define SMEM_BYTES (2 * 128 * SROW * 2)

__device__ __forceinline__ const __half* front_B(int z) {
    if (z == 0) return g_wh + OFF_WATT;
    if (z <= 8) return g_wh + OFF_XR + (long)(z - 1) * HID * HID;
    return g_wh + OFF_ROOT;
}

__global__ __launch_bounds__(256, 2)
void gemm_front(const __half* __restrict__ A, const float* __restrict__ bias,
                int M, int Nn) {
    extern __shared__ __half sm[];
    __half* As = sm;
    __half* Bs = sm + 128 * SROW;

    const int m0 = blockIdx.x * 128;
    const int tid = threadIdx.x;
    const int lane = tid & 31, wid = tid >> 5;
    const int wm = wid >> 2, wn = wid & 3;
    const int g = lane >> 2, tg = lane & 3;

    unsigned as_base = (unsigned)__cvta_generic_to_shared(As);
    unsigned bs_base = (unsigned)__cvta_generic_to_shared(Bs);
    const int a_row = (lane & 15);
    const int a_koff = (lane >> 4) << 3;
    const int b_krow = (lane & 15);

    #pragma unroll
    for (int l = 0; l < 8; l++) {
        int idx = tid + l * 256;
        int row = idx >> 4, q = idx & 15;
        bool ok = (m0 + row < M);
        const __half* src = A + (ok ? ((long)(m0 + row) * HID + q * 8) : 0);
        unsigned dst = as_base + ((unsigned)(row * SROW + q * 8) << 1);
        int sz = ok ? 16 : 0;
        asm volatile("cp.async.ca.shared.global [%0], [%1], 16, %2;"
                     :: "r"(dst), "l"(src), "r"(sz));
    }
    {
        const __half* Bz = front_B(0);
        #pragma unroll
        for (int l = 0; l < 8; l++) {
            int idx = tid + l * 256;
            int row = idx >> 4, q = idx & 15;
            unsigned dst = bs_base + ((unsigned)(row * SROW + q * 8) << 1);
            asm volatile("cp.async.ca.shared.global [%0], [%1], 16;"
                         :: "r"(dst), "l"(Bz + (long)row * HID + q * 8));
        }
    }
    asm volatile("cp.async.commit_group;");

    for (int z = 0; z < 10; z++) {
        asm volatile("cp.async.wait_group 0;");
        __syncthreads();

        float acc[4][4][4];
        #pragma unroll
        for (int i = 0; i < 4; i++)
            #pragma unroll
            for (int j = 0; j < 4; j++)
                #pragma unroll
                for (int c = 0; c < 4; c++) acc[i][j][c] = 0.0f;

        #pragma unroll
        for (int kk = 0; kk < 8; kk++) {
            const int k16 = kk * 16;
            unsigned af[4][4], bf[4][2];
            #pragma unroll
            for (int tm = 0; tm < 4; tm++) {
                int rb = wm * 64 + tm * 16;
                unsigned addr = as_base + (((rb + a_row) * SROW + k16 + a_koff) << 1);
                asm volatile(
                    "ldmatrix.sync.aligned.m8n8.x4.shared.b16 {%0,%1,%2,%3}, [%4];"
                    : "=r"(af[tm][0]), "=r"(af[tm][1]),
                      "=r"(af[tm][2]), "=r"(af[tm][3])
                    : "r"(addr));
            }
            #pragma unroll
            for (int tn = 0; tn < 4; tn++) {
                int cb = wn * 32 + tn * 8;
                unsigned addr = bs_base + (((k16 + b_krow) * SROW + cb) << 1);
                asm volatile(
                    "ldmatrix.sync.aligned.m8n8.x2.trans.shared.b16 {%0,%1}, [%2];"
                    : "=r"(bf[tn][0]), "=r"(bf[tn][1])
                    : "r"(addr));
            }
            #pragma unroll
            for (int tm = 0; tm < 4; tm++)
                #pragma unroll
                for (int tn = 0; tn < 4; tn++) {
                    asm volatile(
                        "mma.sync.aligned.m16n8k16.row.col.f32.f16.f16.f32 "
                        "{%0,%1,%2,%3}, {%4,%5,%6,%7}, {%8,%9}, {%0,%1,%2,%3};"
                        : "+f"(acc[tm][tn][0]), "+f"(acc[tm][tn][1]),
                          "+f"(acc[tm][tn][2]), "+f"(acc[tm][tn][3])
                        : "r"(af[tm][0]), "r"(af[tm][1]),
                          "r"(af[tm][2]), "r"(af[tm][3]),
                          "r"(bf[tn][0]), "r"(bf[tn][1]));
                }
        }
        __syncthreads();

        if (z < 9) {
            const __half* Bz = front_B(z + 1);
            #pragma unroll
            for (int l = 0; l < 8; l++) {
                int idx = tid + l * 256;
                int row = idx >> 4, q = idx & 15;
                unsigned dst = bs_base + ((unsigned)(row * SROW + q * 8) << 1);
                asm volatile("cp.async.ca.shared.global [%0], [%1], 16;"
                             :: "r"(dst), "l"(Bz + (long)row * HID + q * 8));
            }
            asm volatile("cp.async.commit_group;");
        }

        #pragma unroll
        for (int tm = 0; tm < 4; tm++) {
            int r0 = m0 + wm * 64 + tm * 16 + g;
            #pragma unroll
            for (int tn = 0; tn < 4; tn++) {
                int col = wn * 32 + tn * 8 + 2 * tg;
                float2 bv = make_float2(0.f, 0.f);
                if (z == 9) bv = *(const float2*)(bias + col);
                #pragma unroll
                for (int half_ = 0; half_ < 2; half_++) {
                    int row = r0 + half_ * 8;
                    if (row >= M) continue;
                    float v0 = acc[tm][tn][half_*2+0] + bv.x;
                    float v1 = acc[tm][tn][half_*2+1] + bv.y;
                    if (z >= 1 && z <= 8) {
                        __half* Ch = g_xr + (long)(z - 1) * Nn * HID;
                        __half2 hv = __floats2half2_rn(v0, v1);
                        *(__half2*)(Ch + (long)row * HID + col) = hv;
                    } else if (z == 0) {
                        if (col < 64)
                            *(float2*)(g_ad + (long)row * 64 + col) = make_float2(v0, v1);
                    } else {
                        __half2 hv = __floats2half2_rn(v0, v1);
                        *(__half2*)(g_outc + (long)row * HID + col) = hv;
                    }
                }
            }
        }
    }
}

// -------- FFN1: A resident (K=128), loop 4 n-tiles; GELU -> T fp16 ----------
__global__ __launch_bounds__(256, 2)
void gemm_ffn1(const __half* __restrict__ A, const float* __restrict__ bias,
               __half* __restrict__ T, int M) {
    extern __shared__ __half sm[];
    __half* As = sm;
    __half* Bs = sm + 128 * SROW;

    const int m0 = blockIdx.x * 128;
    const int tid = threadIdx.x;
    const int lane = tid & 31, wid = tid >> 5;
    const int wm = wid >> 2, wn = wid & 3;
    const int g = lane >> 2, tg = lane & 3;

    unsigned as_base = (unsigned)__cvta_generic_to_shared(As);
    unsigned bs_base = (unsigned)__cvta_generic_to_shared(Bs);
    const int a_row = (lane & 15);
    const int a_koff = (lane >> 4) << 3;
    const int b_krow = (lane & 15);

    #pragma unroll
    for (int l = 0; l < 8; l++) {
        int idx = tid + l * 256;
        int row = idx >> 4, q = idx & 15;
        bool ok = (m0 + row < M);
        const __half* src = A + (ok ? ((long)(m0 + row) * HID + q * 8) : 0);
        unsigned dst = as_base + ((unsigned)(row * SROW + q * 8) << 1);
        int sz = ok ? 16 : 0;
        asm volatile("cp.async.ca.shared.global [%0], [%1], 16, %2;"
                     :: "r"(dst), "l"(src), "r"(sz));
    }
    {
        const __half* B0 = g_wh + OFF_FFN1;
        #pragma unroll
        for (int l = 0; l < 8; l++) {
            int idx = tid + l * 256;
            int row = idx >> 4, q = idx & 15;
            unsigned dst = bs_base + ((unsigned)(row * SROW + q * 8) << 1);
            asm volatile("cp.async.ca.shared.global [%0], [%1], 16;"
                         :: "r"(dst), "l"(B0 + (long)row * FFDIM + q * 8));
        }
    }
    asm volatile("cp.async.commit_group;");

    for (int nt = 0; nt < 4; nt++) {
        asm volatile("cp.async.wait_group 0;");
        __syncthreads();

        float acc[4][4][4];
        #pragma unroll
        for (int i = 0; i < 4; i++)
            #pragma unroll
            for (int j = 0; j < 4; j++)
                #pragma unroll
                for (int c = 0; c < 4; c++) acc[i][j][c] = 0.0f;

        #pragma unroll
        for (int kk = 0; kk < 8; kk++) {
            const int k16 = kk * 16;
            unsigned af[4][4], bf[4][2];
            #pragma unroll
            for (int tm = 0; tm < 4; tm++) {
                int rb = wm * 64 + tm * 16;
                unsigned addr = as_base + (((rb + a_row) * SROW + k16 + a_koff) << 1);
                asm volatile(
                    "ldmatrix.sync.aligned.m8n8.x4.shared.b16 {%0,%1,%2,%3}, [%4];"
                    : "=r"(af[tm][0]), "=r"(af[tm][1]),
                      "=r"(af[tm][2]), "=r"(af[tm][3])
                    : "r"(addr));
            }
            #pragma unroll
            for (int tn = 0; tn < 4; tn++) {
                int cb = wn * 32 + tn * 8;
                unsigned addr = bs_base + (((k16 + b_krow) * SROW + cb) << 1);
                asm volatile(
                    "ldmatrix.sync.aligned.m8n8.x2.trans.shared.b16 {%0,%1}, [%2];"
                    : "=r"(bf[tn][0]), "=r"(bf[tn][1])
                    : "r"(addr));
            }
            #pragma unroll
            for (int tm = 0; tm < 4; tm++)
                #pragma unroll
                for (int tn = 0; tn < 4; tn++) {
                    asm volatile(
                        "mma.sync.aligned.m16n8k16.row.col.f32.f16.f16.f32 "
                        "{%0,%1,%2,%3}, {%4,%5,%6,%7}, {%8,%9}, {%0,%1,%2,%3};"
                        : "+f"(acc[tm][tn][0]), "+f"(acc[tm][tn][1]),
                          "+f"(acc[tm][tn][2]), "+f"(acc[tm][tn][3])
                        : "r"(af[tm][0]), "r"(af[tm][1]),
                          "r"(af[tm][2]), "r"(af[tm][3]),
                          "r"(bf[tn][0]), "r"(bf[tn][1]));
                }
        }
        __syncthreads();

        if (nt < 3) {
            const __half* Bn = g_wh + OFF_FFN1 + (nt + 1) * 128;
            #pragma unroll
            for (int l = 0; l < 8; l++) {
                int idx = tid + l * 256;
                int row = idx >> 4, q = idx & 15;
                unsigned dst = bs_base + ((unsigned)(row * SROW + q * 8) << 1);
                asm volatile("cp.async.ca.shared.global [%0], [%1], 16;"
                             :: "r"(dst), "l"(Bn + (long)row * FFDIM + q * 8));
            }
            asm volatile("cp.async.commit_group;");
        }

        #pragma unroll
        for (int tm = 0; tm < 4; tm++) {
            int r0 = m0 + wm * 64 + tm * 16 + g;
            #pragma unroll
            for (int tn = 0; tn < 4; tn++) {
                int col = nt * 128 + wn * 32 + tn * 8 + 2 * tg;
                float2 bv = *(const float2*)(bias + col);
                #pragma unroll
                for (int half_ = 0; half_ < 2; half_++) {
                    int row = r0 + half_ * 8;
                    if (row >= M) continue;
                    float v0 = geluf(acc[tm][tn][half_*2+0] + bv.x);
                    float v1 = geluf(acc[tm][tn][half_*2+1] + bv.y);
                    __half2 hv = __floats2half2_rn(v0, v1);
                    *(__half2*)(T + (long)row * FFDIM + col) = hv;
                }
            }
        }
    }
}

// ---------------- generic fp16 GEMM (FFN2: K=512, ncols=128) ----------------
__global__ __launch_bounds__(256, 2)
void gemm_f16(const __half* __restrict__ A, const __half* __restrict__ B,
              void* __restrict__ C, const float* __restrict__ bias,
              const float* __restrict__ resid,
              int M, int K, int ncols, int act, int outHalf) {
    extern __shared__ __half sm[];
    __half* As = sm;
    __half* Bs = sm + 128 * SROW;

    const int m0 = blockIdx.x * 128;
    const int n0 = blockIdx.y * 128;
    const int tid = threadIdx.x;
    const int lane = tid & 31, wid = tid >> 5;
    const int wm = wid >> 2, wn = wid & 3;
    const int g = lane >> 2, tg = lane & 3;

    float acc[4][4][4];
    #pragma unroll
    for (int i = 0; i < 4; i++)
        #pragma unroll
        for (int j = 0; j < 4; j++)
            #pragma unroll
            for (int c = 0; c < 4; c++) acc[i][j][c] = 0.0f;

    unsigned as_base = (unsigned)__cvta_generic_to_shared(As);
    unsigned bs_base = (unsigned)__cvta_generic_to_shared(Bs);
    const int a_row = (lane & 15);
    const int a_koff = (lane >> 4) << 3;
    const int b_krow = (lane & 15);

    for (int k0 = 0; k0 < K; k0 += 128) {
        if (k0) __syncthreads();
        #pragma unroll
        for (int l = 0; l < 8; l++) {
            int idx = tid + l * 256;
            int row = idx >> 4, q = idx & 15;
            bool ok = (m0 + row < M);
            const __half* src = A + (ok ? ((long)(m0 + row) * K + k0 + q * 8) : 0);
            unsigned dst = as_base + ((unsigned)(row * SROW + q * 8) << 1);
            int sz = ok ? 16 : 0;
            asm volatile("cp.async.ca.shared.global [%0], [%1], 16, %2;"
                         :: "r"(dst), "l"(src), "r"(sz));
        }
        #pragma unroll
        for (int l = 0; l < 8; l++) {
            int idx = tid + l * 256;
            int row = idx >> 4, q = idx & 15;
            const __half* src = B + (long)(k0 + row) * ncols + n0 + q * 8;
            unsigned dst = bs_base + ((unsigned)(row * SROW + q * 8) << 1);
            asm volatile("cp.async.ca.shared.global [%0], [%1], 16;"
                         :: "r"(dst), "l"(src));
        }
        asm volatile("cp.async.commit_group;");
        asm volatile("cp.async.wait_group 0;");
        __syncthreads();

        #pragma unroll
        for (int kk = 0; kk < 8; kk++) {
            const int k16 = kk * 16;
            unsigned af[4][4], bf[4][2];
            #pragma unroll
            for (int tm = 0; tm < 4; tm++) {
                int rb = wm * 64 + tm * 16;
                unsigned addr = as_base + (((rb + a_row) * SROW + k16 + a_koff) << 1);
                asm volatile(
                    "ldmatrix.sync.aligned.m8n8.x4.shared.b16 {%0,%1,%2,%3}, [%4];"
                    : "=r"(af[tm][0]), "=r"(af[tm][1]),
                      "=r"(af[tm][2]), "=r"(af[tm][3])
                    : "r"(addr));
            }
            #pragma unroll
            for (int tn = 0; tn < 4; tn++) {
                int cb = wn * 32 + tn * 8;
                unsigned addr = bs_base + (((k16 + b_krow) * SROW + cb) << 1);
                asm volatile(
                    "ldmatrix.sync.aligned.m8n8.x2.trans.shared.b16 {%0,%1}, [%2];"
                    : "=r"(bf[tn][0]), "=r"(bf[tn][1])
                    : "r"(addr));
            }
            #pragma unroll
            for (int tm = 0; tm < 4; tm++)
                #pragma unroll
                for (int tn = 0; tn < 4; tn++) {
                    asm volatile(
                        "mma.sync.aligned.m16n8k16.row.col.f32.f16.f16.f32 "
                        "{%0,%1,%2,%3}, {%4,%5,%6,%7}, {%8,%9}, {%0,%1,%2,%3};"
                        : "+f"(acc[tm][tn][0]), "+f"(acc[tm][tn][1]),
                          "+f"(acc[tm][tn][2]), "+f"(acc[tm][tn][3])
                        : "r"(af[tm][0]), "r"(af[tm][1]),
                          "r"(af[tm][2]), "r"(af[tm][3]),
                          "r"(bf[tn][0]), "r"(bf[tn][1]));
                }
        }
    }

    #pragma unroll
    for (int tm = 0; tm < 4; tm++) {
        int r0 = m0 + wm * 64 + tm * 16 + g;
        #pragma unroll
        for (int tn = 0; tn < 4; tn++) {
            int col = n0 + wn * 32 + tn * 8 + 2 * tg;
            float2 bv = make_float2(0.f, 0.f);
            if (bias) bv = *(const float2*)(bias + col);
            #pragma unroll
            for (int half_ = 0; half_ < 2; half_++) {
                int row = r0 + half_ * 8;
                if (row >= M) continue;
                float v0 = acc[tm][tn][half_*2+0] + bv.x;
                float v1 = acc[tm][tn][half_*2+1] + bv.y;
                if (act == 1) { v0 = geluf(v0); v1 = geluf(v1); }
                if (resid) {
                    float2 rr = *(const float2*)(resid + (long)row * ncols + col);
                    v0 += rr.x; v1 += rr.y;
                }
                if (outHalf) {
                    __half2 hv = __floats2half2_rn(v0, v1);
                    *(__half2*)((__half*)C + (long)row * ncols + col) = hv;
                } else {
                    *(float2*)((float*)C + (long)row * ncols + col) = make_float2(v0, v1);
                }
            }
        }
    }
}

// ------ fused aggregation (round-14 form) with node-range [off, off+cnt) ------
__global__ void aggregate_kernel(const float* __restrict__ x,
                                 const float* __restrict__ w,
                                 const float* __restrict__ b,
                                 float* __restrict__ x1out,
                                 int off, int cnt, int Nn) {
    int gw = (blockIdx.x * blockDim.x + threadIdx.x) >> 5;
    int lane = threadIdx.x & 31;
    if (gw >= cnt) return;
    long node = off + gw;
    int h = lane >> 3;
    float adv = g_ad[node * 64 + 32 + lane] + g_er[lane];
    int beg = g_start[node];
    int end = beg + g_deg[node];
    float den = 0.0f;
    float a0 = 0.f, a1 = 0.f, a2 = 0.f, a3 = 0.f;
    int e = beg;
    for (; e + 4 <= end; e += 4) {
        int rec[4];
        #pragma unroll
        for (int j = 0; j < 4; j++) rec[j] = __ldg(&g_rec[e + j]);
        int sidx[4], ridx[4];
        float ads[4];
        uint2 raw[4];
        #pragma unroll
        for (int j = 0; j < 4; j++) {
            sidx[j] = rec[j] & 0xFFFF;
            ridx[j] = rec[j] >> 16;
            ads[j] = __ldg(&g_ad[(long)sidx[j] * 64 + ridx[j] * 4 + h]);
            raw[j] = *(const uint2*)(g_xr + ((long)ridx[j] * Nn + sidx[j]) * HID + lane * 4);
        }
        #pragma unroll
        for (int j = 0; j < 4; j++) {
            float logit = __shfl_sync(0xffffffffu, adv, ridx[j] * 4 + h) + ads[j];
            float ex = __expf(lreluf(logit));
            den += ex;
            float2 p01 = __half22float2(*(__half2*)&raw[j].x);
            float2 p23 = __half22float2(*(__half2*)&raw[j].y);
            a0 += p01.x * ex; a1 += p01.y * ex;
            a2 += p23.x * ex; a3 += p23.y * ex;
        }
    }
    for (; e < end; e++) {
        int rec = __ldg(&g_rec[e]);
        int s = rec & 0xFFFF, r = rec >> 16;
        float logit = __shfl_sync(0xffffffffu, adv, r * 4 + h)
                    + __ldg(&g_ad[(long)s * 64 + r * 4 + h]);
        float ex = __expf(lreluf(logit));
        den += ex;
        uint2 raw = *(const uint2*)(g_xr + ((long)r * Nn + s) * HID + lane * 4);
        float2 p01 = __half22float2(*(__half2*)&raw.x);
        float2 p23 = __half22float2(*(__half2*)&raw.y);
        a0 += p01.x * ex; a1 += p01.y * ex;
        a2 += p23.x * ex; a3 += p23.y * ex;
    }
    float inv = 1.0f / (den + 1e-16f);
    uint2 rtr = *(const uint2*)(g_outc + (size_t)node * HID + lane * 4);
    float2 r01 = __half22float2(*(__half2*)&rtr.x);
    float2 r23 = __half22float2(*(__half2*)&rtr.y);
    float4 oc;
    oc.x = eluf(a0 * inv + r01.x);
    oc.y = eluf(a1 * inv + r01.y);
    oc.z = eluf(a2 * inv + r23.x);
    oc.w = eluf(a3 * inv + r23.y);
    float4 xv = *(const float4*)(x + (size_t)node * HID + lane * 4);
    float4 x1 = make_float4(xv.x + oc.x, xv.y + oc.y, xv.z + oc.z, xv.w + oc.w);
    *(float4*)(x1out + (size_t)node * HID + lane * 4) = x1;
    float s = x1.x + x1.y + x1.z + x1.w;
    float q = x1.x * x1.x + x1.y * x1.y + x1.z * x1.z + x1.w * x1.w;
    #pragma unroll
    for (int o = 16; o; o >>= 1) {
        s += __shfl_xor_sync(0xffffffffu, s, o);
        q += __shfl_xor_sync(0xffffffffu, q, o);
    }
    float mu = s * (1.0f / HID);
    float var = q * (1.0f / HID) - mu * mu;
    float rstd = rsqrtf(var + 1e-5f);
    float4 wv = *(const float4*)(w + lane * 4);
    float4 bv = *(const float4*)(b + lane * 4);
    __half2 o01 = __floats2half2_rn((x1.x - mu) * rstd * wv.x + bv.x,
                                    (x1.y - mu) * rstd * wv.y + bv.y);
    __half2 o23 = __floats2half2_rn((x1.z - mu) * rstd * wv.z + bv.z,
                                    (x1.w - mu) * rstd * wv.w + bv.w);
    *(uint2*)(g_h2 + (size_t)node * HID + lane * 4) =
        make_uint2(*(unsigned*)&o01, *(unsigned*)&o23);
}

// ---------------- launch ----------------
extern "C" void kernel_launch(void* const* d_in, const int* in_sizes, int n_in,
                              void* d_out, int out_size) {
    const float* x          = (const float*)d_in[0];
    const float* weight     = (const float*)d_in[1];
    const float* root_w     = (const float*)d_in[2];
    const float* edge_emb   = (const float*)d_in[3];
    const float* att_src    = (const float*)d_in[4];
    const float* att_dst    = (const float*)d_in[5];
    const float* att_edge   = (const float*)d_in[6];
    const float* bias       = (const float*)d_in[7];
    const float* n1w        = (const float*)d_in[8];
    const float* n1b        = (const float*)d_in[9];
    const float* n2w        = (const float*)d_in[10];
    const float* n2b        = (const float*)d_in[11];
    const float* ffn_w1     = (const float*)d_in[12];
    const float* ffn_b1     = (const float*)d_in[13];
    const float* ffn_w2     = (const float*)d_in[14];
    const float* ffn_b2     = (const float*)d_in[15];
    const int*   edge_index = (const int*)d_in[16];
    const int*   edge_type  = (const int*)d_in[17];
    float* out = (float*)d_out;

    int N = in_sizes[0] / HID;
    int E = in_sizes[17];

    static cudaStream_t s2 = nullptr;
    static cudaEvent_t ev_start = nullptr, ev_prep = nullptr, ev_csr = nullptr;
    static cudaEvent_t ev_agg0 = nullptr, ev_s2done = nullptr;
    if (!s2) {
        cudaFuncSetAttribute(gemm_front,
            cudaFuncAttributeMaxDynamicSharedMemorySize, SMEM_BYTES);
        cudaFuncSetAttribute(gemm_ffn1,
            cudaFuncAttributeMaxDynamicSharedMemorySize, SMEM_BYTES);
        cudaFuncSetAttribute(gemm_f16,
            cudaFuncAttributeMaxDynamicSharedMemorySize, SMEM_BYTES);
        cudaStreamCreateWithFlags(&s2, cudaStreamNonBlocking);
        cudaEventCreateWithFlags(&ev_start, cudaEventDisableTiming);
        cudaEventCreateWithFlags(&ev_prep, cudaEventDisableTiming);
        cudaEventCreateWithFlags(&ev_csr, cudaEventDisableTiming);
        cudaEventCreateWithFlags(&ev_agg0, cudaEventDisableTiming);
        cudaEventCreateWithFlags(&ev_s2done, cudaEventDisableTiming);
    }

    __half *p_h1, *p_h2, *p_t, *p_wh;
    cudaGetSymbolAddress((void**)&p_h1, g_h1);
    cudaGetSymbolAddress((void**)&p_h2, g_h2);
    cudaGetSymbolAddress((void**)&p_t,  g_t);
    cudaGetSymbolAddress((void**)&p_wh, g_wh);

    int rowBlocks = (N + 7) / 8;
    int mTiles    = (N + 127) / 128;

    // half split (first half multiple of 128)
    int Nh = ((N / 2 + 127) / 128) * 128;
    if (Nh > N) Nh = N;
    int N1 = N - Nh;
    int mT0 = (Nh + 127) / 128;
    int mT1 = (N1 + 127) / 128;
    int rb0 = (Nh + 7) / 8;
    int rb1 = (N1 + 7) / 8;

    // fork: prep + CSR chain on s2
    cudaEventRecord(ev_start, 0);
    cudaStreamWaitEvent(s2, ev_start, 0);
    prep_kernel<<<(P_END + 255) / 256, 256, 0, s2>>>(
        weight, root_w, ffn_w1, ffn_w2, att_src, att_dst, att_edge, edge_emb);
    cudaEventRecord(ev_prep, s2);
    zero_kernel<<<(N + 255) / 256, 256, 0, s2>>>(N);
    hist_kernel<<<(E + 255) / 256, 256, 0, s2>>>(edge_index, E);
    alloc_kernel<<<(N + 255) / 256, 256, 0, s2>>>(N);
    scatter_kernel<<<(E + 255) / 256, 256, 0, s2>>>(edge_index, edge_type, E);
    cudaEventRecord(ev_csr, s2);

    // main: LN || prep, front GEMM
    ln_kernel<<<rowBlocks, 256>>>(x, n1w, n1b, p_h1, N);
    cudaStreamWaitEvent(0, ev_prep, 0);
    gemm_front<<<mTiles, 256, SMEM_BYTES>>>(p_h1, bias, N, N);

    // aggregate half0, then half1 (main); FFN(half0) on s2 overlapping agg half1
    cudaStreamWaitEvent(0, ev_csr, 0);
    aggregate_kernel<<<rb0, 256>>>(x, n2w, n2b, out, 0, Nh, N);
    cudaEventRecord(ev_agg0, 0);
    if (N1 > 0)
        aggregate_kernel<<<rb1, 256>>>(x, n2w, n2b, out, Nh, N1, N);

    cudaStreamWaitEvent(s2, ev_agg0, 0);
    gemm_ffn1<<<mT0, 256, SMEM_BYTES, s2>>>(p_h2, ffn_b1, p_t, Nh);
    gemm_f16<<<dim3(mT0, 1, 1), 256, SMEM_BYTES, s2>>>(
        p_t, p_wh + OFF_FFN2, out, ffn_b2, out, Nh, FFDIM, HID, 0, 0);
    cudaEventRecord(ev_s2done, s2);

    if (N1 > 0) {
        gemm_ffn1<<<mT1, 256, SMEM_BYTES>>>(p_h2 + (long)Nh * HID, ffn_b1,
                                            p_t + (long)Nh * FFDIM, N1);
        gemm_f16<<<dim3(mT1, 1, 1), 256, SMEM_BYTES>>>(
            p_t + (long)Nh * FFDIM, p_wh + OFF_FFN2, out + (long)Nh * HID,
            ffn_b2, out + (long)Nh * HID, N1, FFDIM, HID, 0, 0);
    }
    cudaStreamWaitEvent(0, ev_s2done, 0);
}